// round 5
// baseline (speedup 1.0000x reference)
#include <cuda_runtime.h>
#include <cuda_bf16.h>
#include <cstdint>

// ---------------- problem constants ----------------
#define BATCH   2
#define SEQ     2048
#define TOK     (BATCH * SEQ)        // 4096
#define DM      768                  // d_model
#define DI      1536                 // d_inner
#define DI2     (2 * DI)             // 3072
#define NSTATE  16
#define NX      33                   // 1 + 2*NSTATE
#define DCONV   4

typedef __nv_bfloat16 bf16;

// ---------------- scratch (static device globals) --------
__device__ __align__(16) bf16  g_xn_h [TOK * DM];
__device__ __align__(16) bf16  g_xn_l [TOK * DM];
__device__ __align__(16) bf16  g_win_h[2ll * DI2 * DM];   // [dir][N=3072][K=768]
__device__ __align__(16) bf16  g_win_l[2ll * DI2 * DM];
__device__ __align__(16) bf16  g_wout_h[2ll * DM * DI];   // [dir][N=768][K=1536]
__device__ __align__(16) bf16  g_wout_l[2ll * DM * DI];
__device__ __align__(16) bf16  g_gh [2ll * TOK * DI];
__device__ __align__(16) bf16  g_gl [2ll * TOK * DI];
__device__ float  g_xz [2ll * TOK * DI2];
__device__ float  g_xc [2ll * TOK * DI];
__device__ __align__(16) float2 g_bc [2ll * TOK * NSTATE];  // (B_s, C_s) packed
__device__ __align__(16) float2 g_du [2ll * TOK * DI];      // (dt, dt*xc) packed
__device__ float  g_yp [2ll * TOK * DM];

// ================= helpers =================
__device__ __forceinline__ uint32_t s2u(const void* p) {
    uint32_t a;
    asm("{ .reg .u64 t; cvta.to.shared.u64 t, %1; cvt.u32.u64 %0, t; }"
        : "=r"(a) : "l"(p));
    return a;
}
__device__ __forceinline__ uint32_t swz(uint32_t off) {
    return off ^ ((off >> 3) & 0x70);
}
__device__ __forceinline__ void cpasync16(uint32_t dst, const void* src) {
    asm volatile("cp.async.cg.shared.global [%0], [%1], 16;" :: "r"(dst), "l"(src) : "memory");
}
#define CP_COMMIT() asm volatile("cp.async.commit_group;" ::: "memory")
#define CP_WAIT0()  asm volatile("cp.async.wait_group 0;" ::: "memory")
#define CP_WAIT1()  asm volatile("cp.async.wait_group 1;" ::: "memory")

__device__ __forceinline__ void ldsm4(uint32_t* r, uint32_t addr) {
    asm volatile("ldmatrix.sync.aligned.m8n8.x4.shared.b16 {%0,%1,%2,%3}, [%4];"
                 : "=r"(r[0]), "=r"(r[1]), "=r"(r[2]), "=r"(r[3]) : "r"(addr));
}
__device__ __forceinline__ void mma16816(float* c, const uint32_t* a,
                                         uint32_t b0, uint32_t b1) {
    asm volatile(
        "mma.sync.aligned.m16n8k16.row.col.f32.bf16.bf16.f32 "
        "{%0,%1,%2,%3}, {%4,%5,%6,%7}, {%8,%9}, {%0,%1,%2,%3};"
        : "+f"(c[0]), "+f"(c[1]), "+f"(c[2]), "+f"(c[3])
        : "r"(a[0]), "r"(a[1]), "r"(a[2]), "r"(a[3]), "r"(b0), "r"(b1));
}

// ================= mma.sync GEMM (bf16x3 split, 3-stage pipeline) =========
// C[dir][M][N] (fp32) = A(hi+lo)[M][K] @ B(hi+lo)[dir][N][K]^T
#define BK 64
#define TILE_B 16384                 // 128 rows x 128 bytes
#define STAGE_B (4 * TILE_B)         // Ah, Al, Bh, Bl
#define NSTG 3

__global__ __launch_bounds__(256, 1)
void mma_gemm(const bf16* __restrict__ Ah, const bf16* __restrict__ Al,
              const bf16* __restrict__ Bh, const bf16* __restrict__ Bl,
              float* __restrict__ C, int M, int N, int K, int aPerDir, int flipA)
{
    extern __shared__ __align__(1024) char smem[];
    const int dir   = blockIdx.z;
    const int mBase = blockIdx.y * 128;
    const int nBase = blockIdx.x * 128;
    const uint32_t sb = s2u(smem);
    const int tid = threadIdx.x, wid = tid >> 5, lane = tid & 31;
    const int wm = wid & 3, wn = wid >> 2;

    const bf16* Ahp = Ah + (aPerDir ? (size_t)dir * M * K : 0);
    const bf16* Alp = Al + (aPerDir ? (size_t)dir * M * K : 0);
    const bf16* Bhp = Bh + (size_t)dir * (size_t)N * K;
    const bf16* Blp = Bl + (size_t)dir * (size_t)N * K;

    const int CK = K / BK;

    float acc[2][8][4];
    #pragma unroll
    for (int i = 0; i < 2; i++)
        #pragma unroll
        for (int j = 0; j < 8; j++)
            #pragma unroll
            for (int q = 0; q < 4; q++) acc[i][j][q] = 0.f;

    auto issue = [&](int c, int st) {
        const int k0 = c * BK;
        #pragma unroll
        for (int i = 0; i < 16; ++i) {
            int q     = tid + 256 * i;
            int which = q >> 10;            // 0 Ah, 1 Al, 2 Bh, 3 Bl
            int t     = q & 1023;
            int row   = t >> 3;
            int kb    = t & 7;
            const bf16* src;
            if (which < 2) {
                int grow = mBase + row;
                if (flipA && dir) grow ^= (SEQ - 1);
                src = (which ? Alp : Ahp) + (size_t)grow * K + k0 + kb * 8;
            } else {
                src = ((which == 3) ? Blp : Bhp) + (size_t)(nBase + row) * K + k0 + kb * 8;
            }
            uint32_t dst = sb + st * STAGE_B + which * TILE_B +
                           swz((uint32_t)(row * 128 + kb * 16));
            cpasync16(dst, src);
        }
        CP_COMMIT();
    };

    issue(0, 0);
    issue(1, 1);

    const int g  = lane >> 3;    // 8x8-tile group 0..3
    const int lr = lane & 7;

    int stg = 0, stgNext = 2;
    for (int c = 0; c < CK; ++c) {
        if (c + 1 < CK) { CP_WAIT1(); } else { CP_WAIT0(); }
        __syncthreads();
        if (c + 2 < CK) {
            issue(c + 2, stgNext);
            if (++stgNext == NSTG) stgNext = 0;
        }

        const uint32_t tb = sb + stg * STAGE_B;
        if (++stg == NSTG) stg = 0;

        #pragma unroll
        for (int ks = 0; ks < 4; ++ks) {
            const int kByte = ks * 32 + (g >> 1) * 16;
            uint32_t bh[4][4], bl[4][4];
            #pragma unroll
            for (int j = 0; j < 4; ++j) {
                int row = wn * 64 + j * 16 + (g & 1) * 8 + lr;
                uint32_t off = swz((uint32_t)(row * 128 + kByte));
                ldsm4(bh[j], tb + 2 * TILE_B + off);
                ldsm4(bl[j], tb + 3 * TILE_B + off);
            }
            #pragma unroll
            for (int i = 0; i < 2; ++i) {
                int row = wm * 32 + i * 16 + (g & 1) * 8 + lr;
                uint32_t off = swz((uint32_t)(row * 128 + kByte));
                uint32_t ah[4], al[4];
                ldsm4(ah, tb + off);
                ldsm4(al, tb + TILE_B + off);
                #pragma unroll
                for (int j = 0; j < 4; ++j) {
                    mma16816(acc[i][2*j],   ah, bh[j][0], bh[j][2]);
                    mma16816(acc[i][2*j+1], ah, bh[j][1], bh[j][3]);
                    mma16816(acc[i][2*j],   ah, bl[j][0], bl[j][2]);
                    mma16816(acc[i][2*j+1], ah, bl[j][1], bl[j][3]);
                    mma16816(acc[i][2*j],   al, bh[j][0], bh[j][2]);
                    mma16816(acc[i][2*j+1], al, bh[j][1], bh[j][3]);
                }
            }
        }
        __syncthreads();
    }

    // epilogue: direct STG
    float* Cp = C + (size_t)dir * (size_t)M * N;
    #pragma unroll
    for (int i = 0; i < 2; ++i) {
        int r0 = mBase + wm * 32 + i * 16 + (lane >> 2);
        #pragma unroll
        for (int j = 0; j < 8; ++j) {
            int col = nBase + wn * 64 + j * 8 + (lane & 3) * 2;
            float2 v0 = make_float2(acc[i][j][0], acc[i][j][1]);
            float2 v1 = make_float2(acc[i][j][2], acc[i][j][3]);
            *reinterpret_cast<float2*>(Cp + (size_t)r0 * N + col)       = v0;
            *reinterpret_cast<float2*>(Cp + (size_t)(r0 + 8) * N + col) = v1;
        }
    }
}

// ================= layernorm -> bf16 hi/lo =================
__device__ __forceinline__ float block_sum(float v, float* sh) {
    int lane = threadIdx.x & 31, w = threadIdx.x >> 5;
    #pragma unroll
    for (int o = 16; o; o >>= 1) v += __shfl_xor_sync(0xffffffffu, v, o);
    if (lane == 0) sh[w] = v;
    __syncthreads();
    if (w == 0) {
        float x = (lane < 8) ? sh[lane] : 0.f;
        #pragma unroll
        for (int o = 4; o; o >>= 1) x += __shfl_xor_sync(0xffffffffu, x, o);
        if (lane == 0) sh[0] = x;
    }
    __syncthreads();
    float r = sh[0];
    __syncthreads();
    return r;
}

__global__ __launch_bounds__(256) void ln_kernel(
    const float* __restrict__ x, const float* __restrict__ gam,
    const float* __restrict__ bet, bf16* __restrict__ xh, bf16* __restrict__ xl)
{
    __shared__ float sh[8];
    int tok = blockIdx.x;
    const float* xr = x + (size_t)tok * DM;
    int tid = threadIdx.x;
    float v0 = xr[tid], v1 = xr[tid + 256], v2 = xr[tid + 512];
    float s = block_sum(v0 + v1 + v2, sh);
    float mu = s * (1.0f / DM);
    float d0 = v0 - mu, d1 = v1 - mu, d2 = v2 - mu;
    float vs = block_sum(d0 * d0 + d1 * d1 + d2 * d2, sh);
    float inv = rsqrtf(vs * (1.0f / DM) + 1e-5f);
    size_t ob = (size_t)tok * DM;
    #pragma unroll
    for (int p = 0; p < 3; ++p) {
        int i = tid + p * 256;
        float d = (p == 0 ? d0 : p == 1 ? d1 : d2);
        float val = d * inv * gam[i] + bet[i];
        bf16 h = __float2bfloat16(val);
        xh[ob + i] = h;
        xl[ob + i] = __float2bfloat16(val - __bfloat162float(h));
    }
}

// ================= weight transpose + bf16 split =================
__global__ void wsplit_kernel(const float* __restrict__ w0, const float* __restrict__ w1,
                              bf16* __restrict__ th, bf16* __restrict__ tl, int K, int N)
{
    __shared__ float t[32][33];
    int dir = blockIdx.z;
    const float* w = dir ? w1 : w0;
    int k0 = blockIdx.y * 32, n0 = blockIdx.x * 32;
    int tx = threadIdx.x, ty = threadIdx.y;
    #pragma unroll
    for (int i = 0; i < 4; ++i)
        t[ty + 8 * i][tx] = w[(size_t)(k0 + ty + 8 * i) * N + n0 + tx];
    __syncthreads();
    bf16* thp = th + (size_t)dir * N * K;
    bf16* tlp = tl + (size_t)dir * N * K;
    #pragma unroll
    for (int i = 0; i < 4; ++i) {
        int n = n0 + ty + 8 * i, k = k0 + tx;
        float v = t[tx][ty + 8 * i];
        bf16 h = __float2bfloat16(v);
        thp[(size_t)n * K + k] = h;
        tlp[(size_t)n * K + k] = __float2bfloat16(v - __bfloat162float(h));
    }
}

// ================= depthwise causal conv (k=4) + bias + SiLU =================
__global__ __launch_bounds__(256) void conv_silu_kernel(
    const float* __restrict__ xz, const float* __restrict__ cw0,
    const float* __restrict__ cw1, const float* __restrict__ cb0,
    const float* __restrict__ cb1, float* __restrict__ xc)
{
    int dir = blockIdx.z;
    int idx = blockIdx.x * blockDim.x + threadIdx.x;
    if (idx >= TOK * DI) return;
    int tok = idx / DI;
    int d   = idx - tok * DI;
    int l   = tok & (SEQ - 1);
    const float* cw = (dir ? cw1 : cw0) + d * DCONV;
    float acc = (dir ? cb1 : cb0)[d];
    const float* xzp = xz + (size_t)dir * TOK * DI2 + (size_t)tok * DI2 + d;
    #pragma unroll
    for (int j = 0; j < DCONV; j++) {
        int lo = l - (DCONV - 1) + j;
        if (lo >= 0) acc = fmaf(cw[j], xzp[(long)(j - (DCONV - 1)) * DI2], acc);
    }
    float sg = 1.f / (1.f + __expf(-acc));
    xc[(size_t)dir * TOK * DI + idx] = acc * sg;
}

// ===== bcdt (xc @ xw, xw staged in smem) + packed BC + fused dt/u ==========
__global__ __launch_bounds__(256) void bcdt_kernel(
    const float* __restrict__ xc, const float* __restrict__ xw0,
    const float* __restrict__ xw1, const float* __restrict__ dtw0,
    const float* __restrict__ dtw1, const float* __restrict__ dtb0,
    const float* __restrict__ dtb1, float2* __restrict__ bc,
    float2* __restrict__ du)
{
    __shared__ float sw[256 * NX];   // 33 KB
    int dir  = blockIdx.z;
    int warp = threadIdx.x >> 5;
    int lane = threadIdx.x & 31;
    int tok  = blockIdx.x * 8 + warp;
    const float* xw = dir ? xw1 : xw0;
    const float* xr = xc + ((size_t)dir * TOK + tok) * DI;
    float acc = 0.f, acc32 = 0.f;
    for (int kc = 0; kc < DI; kc += 256) {
        __syncthreads();
        for (int i = threadIdx.x; i < 256 * NX; i += 256)
            sw[i] = xw[(size_t)kc * NX + i];
        __syncthreads();
        #pragma unroll 4
        for (int k = 0; k < 256; k += 4) {
            float4 xv = *reinterpret_cast<const float4*>(xr + kc + k);
            const float* wr = sw + k * NX;
            acc = fmaf(xv.x, wr[lane],          acc);
            acc = fmaf(xv.y, wr[NX + lane],     acc);
            acc = fmaf(xv.z, wr[2 * NX + lane], acc);
            acc = fmaf(xv.w, wr[3 * NX + lane], acc);
            if (lane == 0) {
                acc32 = fmaf(xv.x, wr[32],          acc32);
                acc32 = fmaf(xv.y, wr[NX + 32],     acc32);
                acc32 = fmaf(xv.z, wr[2 * NX + 32], acc32);
                acc32 = fmaf(xv.w, wr[3 * NX + 32], acc32);
            }
        }
    }
    const unsigned full = 0xffffffffu;
    // cols: 0 = dt_raw, 1..16 = B_0..15, 17..32 = C_0..15 (col 32 in acc32)
    float dtraw = __shfl_sync(full, acc, 0);
    float Bs = __shfl_sync(full, acc, (lane & 15) + 1);
    float Cs = __shfl_sync(full, acc, (lane & 15) + 17);
    float c15 = __shfl_sync(full, acc32, 0);
    if ((lane & 15) == 15) Cs = c15;
    if (lane < 16)
        bc[((size_t)dir * TOK + tok) * NSTATE + lane] = make_float2(Bs, Cs);

    // fused dt = softplus(dtraw*dtw + dtb); u = dt * xc
    const float* dtw = dir ? dtw1 : dtw0;
    const float* dtb = dir ? dtb1 : dtb0;
    float2* dup = du + ((size_t)dir * TOK + tok) * DI;
    for (int d = lane; d < DI; d += 32) {
        float pre = fmaf(dtraw, dtw[d], dtb[d]);
        float dtv = (pre > 20.f) ? pre : log1pf(__expf(pre));
        dup[d] = make_float2(dtv, dtv * xr[d]);
    }
}

// ===== selective scan + fused gate: 4 ch/warp, 8 lanes/ch, 2 states/lane ===
__global__ __launch_bounds__(128) void scan_gate_kernel(
    const float2* __restrict__ du, const float2* __restrict__ bc,
    const float* __restrict__ xc, const float* __restrict__ xz,
    const float* __restrict__ Alog0, const float* __restrict__ Alog1,
    const float* __restrict__ Dp0, const float* __restrict__ Dp1,
    bf16* __restrict__ gh, bf16* __restrict__ gl)
{
    const unsigned full = 0xffffffffu;
    int w    = blockIdx.x * 4 + (threadIdx.x >> 5);   // 0..1535
    int lane = threadIdx.x & 31;
    int grp  = lane >> 3;        // channel within warp
    int li   = lane & 7;
    int s0   = li * 2;

    int dir = w / 768;
    int rem = w - dir * 768;
    int b   = rem / 384;
    int d   = (rem - b * 384) * 4 + grp;

    const float* Alog = dir ? Alog1 : Alog0;
    float a0 = fminf(fmaxf(Alog[d * NSTATE + s0],     -6.f), 6.f);
    float a1 = fminf(fmaxf(Alog[d * NSTATE + s0 + 1], -6.f), 6.f);
    float Av0 = -__expf(a0), Av1 = -__expf(a1);
    float Dv = (dir ? Dp1 : Dp0)[d];

    size_t tokBase = (size_t)dir * TOK + (size_t)b * SEQ;
    const float2* dup = du + tokBase * DI + d;
    const float2* bcp = bc + tokBase * NSTATE + s0;
    const float*  xcp = xc + tokBase * DI + d;
    const float*  zp  = xz + tokBase * DI2 + DI + d;
    bf16* ghp = gh + tokBase * DI + d;
    bf16* glp = gl + tokBase * DI + d;
    bool leader = (li == 0);

    // depth-2 prefetch pipeline
    float2 duv[2]; float4 bcv[2]; float xcv[2], zv[2];
    #pragma unroll
    for (int j = 0; j < 2; ++j) {
        duv[j] = dup[(size_t)j * DI];
        bcv[j] = *reinterpret_cast<const float4*>(bcp + (size_t)j * NSTATE);
        if (leader) { xcv[j] = xcp[(size_t)j * DI]; zv[j] = zp[(size_t)j * DI2]; }
    }

    float h0 = 0.f, h1 = 0.f;
    #pragma unroll 2
    for (int t = 0; t < SEQ; ++t) {
        int cur = t & 1;
        float2 duc = duv[cur];
        float4 bcc = bcv[cur];
        float xcc = xcv[cur], zc = zv[cur];
        if (t + 2 < SEQ) {
            duv[cur] = dup[(size_t)(t + 2) * DI];
            bcv[cur] = *reinterpret_cast<const float4*>(bcp + (size_t)(t + 2) * NSTATE);
            if (leader) {
                xcv[cur] = xcp[(size_t)(t + 2) * DI];
                zv[cur]  = zp[(size_t)(t + 2) * DI2];
            }
        }
        float e0 = __expf(duc.x * Av0);
        float e1 = __expf(duc.x * Av1);
        h0 = fminf(fmaxf(fmaf(e0, h0, duc.y * bcc.x), -10000.f), 10000.f);
        h1 = fminf(fmaxf(fmaf(e1, h1, duc.y * bcc.z), -10000.f), 10000.f);
        float p = fmaf(h1, bcc.w, h0 * bcc.y);
        p += __shfl_xor_sync(full, p, 4);
        p += __shfl_xor_sync(full, p, 2);
        p += __shfl_xor_sync(full, p, 1);
        if (leader) {
            float y  = fmaf(xcc, Dv, p);
            float sz = zc / (1.f + __expf(-zc));
            float v  = y * sz;
            bf16 hh = __float2bfloat16(v);
            ghp[(size_t)t * DI] = hh;
            glp[(size_t)t * DI] = __float2bfloat16(v - __bfloat162float(hh));
        }
    }
}

// ================= combine =================
__global__ __launch_bounds__(256) void combine_kernel(
    const float* __restrict__ x, const float* __restrict__ alpha,
    const float* __restrict__ yp, float* __restrict__ out)
{
    int idx = blockIdx.x * blockDim.x + threadIdx.x;
    if (idx >= TOK * DM) return;
    int tok = idx / DM;
    int m   = idx - tok * DM;
    float a = 1.f / (1.f + __expf(-alpha[0]));
    int tokb = tok ^ (SEQ - 1);
    float yf = yp[idx];
    float yb = yp[(size_t)TOK * DM + (size_t)tokb * DM + m];
    out[idx] = fmaf(a, yf, fmaf(1.f - a, yb, x[idx]));
}

// ================= launch =================
extern "C" void kernel_launch(void* const* d_in, const int* in_sizes, int n_in,
                              void* d_out, int out_size)
{
    const float* x     = (const float*)d_in[0];
    const float* ln_g  = (const float*)d_in[1];
    const float* ln_b  = (const float*)d_in[2];
    const float* alpha = (const float*)d_in[3];
    const float* f_inw  = (const float*)d_in[4];
    const float* f_cw   = (const float*)d_in[5];
    const float* f_cb   = (const float*)d_in[6];
    const float* f_xw   = (const float*)d_in[7];
    const float* f_dtw  = (const float*)d_in[8];
    const float* f_dtb  = (const float*)d_in[9];
    const float* f_Alog = (const float*)d_in[10];
    const float* f_D    = (const float*)d_in[11];
    const float* f_outw = (const float*)d_in[12];
    const float* b_inw  = (const float*)d_in[13];
    const float* b_cw   = (const float*)d_in[14];
    const float* b_cb   = (const float*)d_in[15];
    const float* b_xw   = (const float*)d_in[16];
    const float* b_dtw  = (const float*)d_in[17];
    const float* b_dtb  = (const float*)d_in[18];
    const float* b_Alog = (const float*)d_in[19];
    const float* b_D    = (const float*)d_in[20];
    const float* b_outw = (const float*)d_in[21];
    float* out = (float*)d_out;

    bf16 *xnh, *xnl, *winh, *winl, *wouth, *woutl, *gh, *gl;
    float *xz, *xc, *yp;
    float2 *bc, *du;
    cudaGetSymbolAddress((void**)&xnh,   g_xn_h);
    cudaGetSymbolAddress((void**)&xnl,   g_xn_l);
    cudaGetSymbolAddress((void**)&winh,  g_win_h);
    cudaGetSymbolAddress((void**)&winl,  g_win_l);
    cudaGetSymbolAddress((void**)&wouth, g_wout_h);
    cudaGetSymbolAddress((void**)&woutl, g_wout_l);
    cudaGetSymbolAddress((void**)&gh,    g_gh);
    cudaGetSymbolAddress((void**)&gl,    g_gl);
    cudaGetSymbolAddress((void**)&xz,    g_xz);
    cudaGetSymbolAddress((void**)&xc,    g_xc);
    cudaGetSymbolAddress((void**)&bc,    g_bc);
    cudaGetSymbolAddress((void**)&du,    g_du);
    cudaGetSymbolAddress((void**)&yp,    g_yp);

    const int smemGemm = NSTG * STAGE_B;   // 192 KB, 3-stage
    cudaFuncSetAttribute(mma_gemm, cudaFuncAttributeMaxDynamicSharedMemorySize, smemGemm);

    // 1) layernorm -> bf16 hi/lo
    ln_kernel<<<TOK, 256>>>(x, ln_g, ln_b, xnh, xnl);

    // 2) weight transpose + split (both dirs)
    wsplit_kernel<<<dim3(DI2 / 32, DM / 32, 2), dim3(32, 8)>>>(
        f_inw, b_inw, winh, winl, DM, DI2);
    wsplit_kernel<<<dim3(DM / 32, DI / 32, 2), dim3(32, 8)>>>(
        f_outw, b_outw, wouth, woutl, DI, DM);

    // 3) in-proj GEMM; dir 1 reads time-flipped rows
    mma_gemm<<<dim3(DI2 / 128, TOK / 128, 2), 256, smemGemm>>>(
        xnh, xnl, winh, winl, xz, TOK, DI2, DM, /*aPerDir=*/0, /*flipA=*/1);

    // 4) depthwise conv + SiLU
    conv_silu_kernel<<<dim3((TOK * DI) / 256, 1, 2), 256>>>(
        xz, f_cw, b_cw, f_cb, b_cb, xc);

    // 5) bcdt + packed BC + fused dt/u
    bcdt_kernel<<<dim3(TOK / 8, 1, 2), 256>>>(
        xc, f_xw, b_xw, f_dtw, b_dtw, f_dtb, b_dtb, bc, du);

    // 6) selective scan + fused gate
    scan_gate_kernel<<<384, 128>>>(
        du, bc, xc, xz, f_Alog, b_Alog, f_D, b_D, gh, gl);

    // 7) out-proj GEMM
    mma_gemm<<<dim3(DM / 128, TOK / 128, 2), 256, smemGemm>>>(
        gh, gl, wouth, woutl, yp, TOK, DM, DI, /*aPerDir=*/1, /*flipA=*/0);

    // 8) combine + residual
    combine_kernel<<<(TOK * DM) / 256, 256>>>(x, alpha, yp, out);
}

// round 6
// speedup vs baseline: 1.1108x; 1.1108x over previous
#include <cuda_runtime.h>
#include <cuda_bf16.h>
#include <cstdint>

// ---------------- problem constants ----------------
#define BATCH   2
#define SEQ     2048
#define TOK     (BATCH * SEQ)        // 4096
#define DM      768                  // d_model
#define DI      1536                 // d_inner
#define DI2     (2 * DI)             // 3072
#define NSTATE  16
#define NX      33                   // 1 + 2*NSTATE
#define DCONV   4

typedef __nv_bfloat16 bf16;

// ---------------- scratch (static device globals) --------
__device__ __align__(16) bf16  g_xn_h [TOK * DM];
__device__ __align__(16) bf16  g_xn_l [TOK * DM];
__device__ __align__(16) bf16  g_win_h[2ll * DI2 * DM];   // [dir][N=3072][K=768]
__device__ __align__(16) bf16  g_win_l[2ll * DI2 * DM];
__device__ __align__(16) bf16  g_wout_h[2ll * DM * DI];   // [dir][N=768][K=1536]
__device__ __align__(16) bf16  g_wout_l[2ll * DM * DI];
__device__ __align__(16) bf16  g_gh [2ll * TOK * DI];
__device__ __align__(16) bf16  g_gl [2ll * TOK * DI];
__device__ float g_xz  [2ll * TOK * DI2];
__device__ float g_xc  [2ll * TOK * DI];
__device__ float g_bcdt[2ll * TOK * NX];
__device__ float g_dt  [2ll * TOK * DI];
__device__ float g_u   [2ll * TOK * DI];
__device__ float g_ys  [2ll * TOK * DI];
__device__ float g_yp  [2ll * TOK * DM];

// ================= helpers =================
__device__ __forceinline__ uint32_t s2u(const void* p) {
    uint32_t a;
    asm("{ .reg .u64 t; cvta.to.shared.u64 t, %1; cvt.u32.u64 %0, t; }"
        : "=r"(a) : "l"(p));
    return a;
}
__device__ __forceinline__ uint32_t swz(uint32_t off) {
    return off ^ ((off >> 3) & 0x70);
}
__device__ __forceinline__ void cpasync16(uint32_t dst, const void* src) {
    asm volatile("cp.async.cg.shared.global [%0], [%1], 16;" :: "r"(dst), "l"(src) : "memory");
}
#define CP_COMMIT() asm volatile("cp.async.commit_group;" ::: "memory")
#define CP_WAIT0()  asm volatile("cp.async.wait_group 0;" ::: "memory")
#define CP_WAIT1()  asm volatile("cp.async.wait_group 1;" ::: "memory")

__device__ __forceinline__ void ldsm4(uint32_t* r, uint32_t addr) {
    asm volatile("ldmatrix.sync.aligned.m8n8.x4.shared.b16 {%0,%1,%2,%3}, [%4];"
                 : "=r"(r[0]), "=r"(r[1]), "=r"(r[2]), "=r"(r[3]) : "r"(addr));
}
__device__ __forceinline__ void mma16816(float* c, const uint32_t* a,
                                         uint32_t b0, uint32_t b1) {
    asm volatile(
        "mma.sync.aligned.m16n8k16.row.col.f32.bf16.bf16.f32 "
        "{%0,%1,%2,%3}, {%4,%5,%6,%7}, {%8,%9}, {%0,%1,%2,%3};"
        : "+f"(c[0]), "+f"(c[1]), "+f"(c[2]), "+f"(c[3])
        : "r"(a[0]), "r"(a[1]), "r"(a[2]), "r"(a[3]), "r"(b0), "r"(b1));
}

// ================= mma.sync GEMM (bf16x3 split, 512 threads) ==============
// C[dir][M][N] (fp32) = A(hi+lo)[M][K] @ B(hi+lo)[dir][N][K]^T
// 128x128 tile, K chunk 64, 3-stage cp.async, 16 warps (4M x 4N, 32x32 each).
#define BK 64
#define TILE_B 16384                 // 128 rows x 128 bytes
#define STAGE_B (4 * TILE_B)         // Ah, Al, Bh, Bl
#define NSTG 3

__global__ __launch_bounds__(512, 1)
void mma_gemm(const bf16* __restrict__ Ah, const bf16* __restrict__ Al,
              const bf16* __restrict__ Bh, const bf16* __restrict__ Bl,
              float* __restrict__ C, int M, int N, int K, int aPerDir, int flipA)
{
    extern __shared__ __align__(1024) char smem[];
    const int dir   = blockIdx.z;
    const int mBase = blockIdx.y * 128;
    const int nBase = blockIdx.x * 128;
    const uint32_t sb = s2u(smem);
    const int tid = threadIdx.x, wid = tid >> 5, lane = tid & 31;
    const int wm = wid & 3, wn = wid >> 2;

    const bf16* Ahp = Ah + (aPerDir ? (size_t)dir * M * K : 0);
    const bf16* Alp = Al + (aPerDir ? (size_t)dir * M * K : 0);
    const bf16* Bhp = Bh + (size_t)dir * (size_t)N * K;
    const bf16* Blp = Bl + (size_t)dir * (size_t)N * K;

    const int CK = K / BK;

    float acc[2][4][4];
    #pragma unroll
    for (int i = 0; i < 2; i++)
        #pragma unroll
        for (int j = 0; j < 4; j++)
            #pragma unroll
            for (int q = 0; q < 4; q++) acc[i][j][q] = 0.f;

    auto issue = [&](int c, int st) {
        const int k0 = c * BK;
        #pragma unroll
        for (int i = 0; i < 8; ++i) {
            int q     = tid + 512 * i;
            int which = q >> 10;            // 0 Ah, 1 Al, 2 Bh, 3 Bl
            int t     = q & 1023;
            int row   = t >> 3;
            int kb    = t & 7;
            const bf16* src;
            if (which < 2) {
                int grow = mBase + row;
                if (flipA && dir) grow ^= (SEQ - 1);
                src = (which ? Alp : Ahp) + (size_t)grow * K + k0 + kb * 8;
            } else {
                src = ((which == 3) ? Blp : Bhp) + (size_t)(nBase + row) * K + k0 + kb * 8;
            }
            uint32_t dst = sb + st * STAGE_B + which * TILE_B +
                           swz((uint32_t)(row * 128 + kb * 16));
            cpasync16(dst, src);
        }
        CP_COMMIT();
    };

    issue(0, 0);
    issue(1, 1);

    const int g  = lane >> 3;    // 8x8-tile group 0..3
    const int lr = lane & 7;

    int stg = 0, stgNext = 2;
    for (int c = 0; c < CK; ++c) {
        if (c + 1 < CK) { CP_WAIT1(); } else { CP_WAIT0(); }
        __syncthreads();
        if (c + 2 < CK) {
            issue(c + 2, stgNext);
            if (++stgNext == NSTG) stgNext = 0;
        }

        const uint32_t tb = sb + stg * STAGE_B;
        if (++stg == NSTG) stg = 0;

        #pragma unroll
        for (int ks = 0; ks < 4; ++ks) {
            const int kByte = ks * 32 + (g >> 1) * 16;
            uint32_t ah[2][4], al[2][4], bh[2][4], bl[2][4];
            #pragma unroll
            for (int jj = 0; jj < 2; ++jj) {
                int row = wn * 32 + jj * 16 + (g & 1) * 8 + lr;
                uint32_t off = swz((uint32_t)(row * 128 + kByte));
                ldsm4(bh[jj], tb + 2 * TILE_B + off);
                ldsm4(bl[jj], tb + 3 * TILE_B + off);
            }
            #pragma unroll
            for (int i = 0; i < 2; ++i) {
                int row = wm * 32 + i * 16 + (g & 1) * 8 + lr;
                uint32_t off = swz((uint32_t)(row * 128 + kByte));
                ldsm4(ah[i], tb + off);
                ldsm4(al[i], tb + TILE_B + off);
            }
            // pass-major ordering: same-acc reuse distance = 8 MMAs
            #pragma unroll
            for (int i = 0; i < 2; ++i)
                #pragma unroll
                for (int jj = 0; jj < 2; ++jj) {
                    mma16816(acc[i][2*jj],   ah[i], bh[jj][0], bh[jj][2]);
                    mma16816(acc[i][2*jj+1], ah[i], bh[jj][1], bh[jj][3]);
                }
            #pragma unroll
            for (int i = 0; i < 2; ++i)
                #pragma unroll
                for (int jj = 0; jj < 2; ++jj) {
                    mma16816(acc[i][2*jj],   ah[i], bl[jj][0], bl[jj][2]);
                    mma16816(acc[i][2*jj+1], ah[i], bl[jj][1], bl[jj][3]);
                }
            #pragma unroll
            for (int i = 0; i < 2; ++i)
                #pragma unroll
                for (int jj = 0; jj < 2; ++jj) {
                    mma16816(acc[i][2*jj],   al[i], bh[jj][0], bh[jj][2]);
                    mma16816(acc[i][2*jj+1], al[i], bh[jj][1], bh[jj][3]);
                }
        }
        __syncthreads();
    }

    // epilogue: direct STG
    float* Cp = C + (size_t)dir * (size_t)M * N;
    #pragma unroll
    for (int i = 0; i < 2; ++i) {
        int r0 = mBase + wm * 32 + i * 16 + (lane >> 2);
        #pragma unroll
        for (int j = 0; j < 4; ++j) {
            int col = nBase + wn * 32 + j * 8 + (lane & 3) * 2;
            float2 v0 = make_float2(acc[i][j][0], acc[i][j][1]);
            float2 v1 = make_float2(acc[i][j][2], acc[i][j][3]);
            *reinterpret_cast<float2*>(Cp + (size_t)r0 * N + col)       = v0;
            *reinterpret_cast<float2*>(Cp + (size_t)(r0 + 8) * N + col) = v1;
        }
    }
}

// ================= layernorm -> bf16 hi/lo =================
__device__ __forceinline__ float block_sum(float v, float* sh) {
    int lane = threadIdx.x & 31, w = threadIdx.x >> 5;
    #pragma unroll
    for (int o = 16; o; o >>= 1) v += __shfl_xor_sync(0xffffffffu, v, o);
    if (lane == 0) sh[w] = v;
    __syncthreads();
    if (w == 0) {
        float x = (lane < 8) ? sh[lane] : 0.f;
        #pragma unroll
        for (int o = 4; o; o >>= 1) x += __shfl_xor_sync(0xffffffffu, x, o);
        if (lane == 0) sh[0] = x;
    }
    __syncthreads();
    float r = sh[0];
    __syncthreads();
    return r;
}

__global__ __launch_bounds__(256) void ln_kernel(
    const float* __restrict__ x, const float* __restrict__ gam,
    const float* __restrict__ bet, bf16* __restrict__ xh, bf16* __restrict__ xl)
{
    __shared__ float sh[8];
    int tok = blockIdx.x;
    const float* xr = x + (size_t)tok * DM;
    int tid = threadIdx.x;
    float v0 = xr[tid], v1 = xr[tid + 256], v2 = xr[tid + 512];
    float s = block_sum(v0 + v1 + v2, sh);
    float mu = s * (1.0f / DM);
    float d0 = v0 - mu, d1 = v1 - mu, d2 = v2 - mu;
    float vs = block_sum(d0 * d0 + d1 * d1 + d2 * d2, sh);
    float inv = rsqrtf(vs * (1.0f / DM) + 1e-5f);
    size_t ob = (size_t)tok * DM;
    #pragma unroll
    for (int p = 0; p < 3; ++p) {
        int i = tid + p * 256;
        float d = (p == 0 ? d0 : p == 1 ? d1 : d2);
        float val = d * inv * gam[i] + bet[i];
        bf16 h = __float2bfloat16(val);
        xh[ob + i] = h;
        xl[ob + i] = __float2bfloat16(val - __bfloat162float(h));
    }
}

// ================= weight transpose + bf16 split =================
__global__ void wsplit_kernel(const float* __restrict__ w0, const float* __restrict__ w1,
                              bf16* __restrict__ th, bf16* __restrict__ tl, int K, int N)
{
    __shared__ float t[32][33];
    int dir = blockIdx.z;
    const float* w = dir ? w1 : w0;
    int k0 = blockIdx.y * 32, n0 = blockIdx.x * 32;
    int tx = threadIdx.x, ty = threadIdx.y;
    #pragma unroll
    for (int i = 0; i < 4; ++i)
        t[ty + 8 * i][tx] = w[(size_t)(k0 + ty + 8 * i) * N + n0 + tx];
    __syncthreads();
    bf16* thp = th + (size_t)dir * N * K;
    bf16* tlp = tl + (size_t)dir * N * K;
    #pragma unroll
    for (int i = 0; i < 4; ++i) {
        int n = n0 + ty + 8 * i, k = k0 + tx;
        float v = t[tx][ty + 8 * i];
        bf16 h = __float2bfloat16(v);
        thp[(size_t)n * K + k] = h;
        tlp[(size_t)n * K + k] = __float2bfloat16(v - __bfloat162float(h));
    }
}

// ================= depthwise causal conv (k=4) + bias + SiLU =================
__global__ __launch_bounds__(256) void conv_silu_kernel(
    const float* __restrict__ xz, const float* __restrict__ cw0,
    const float* __restrict__ cw1, const float* __restrict__ cb0,
    const float* __restrict__ cb1, float* __restrict__ xc)
{
    int dir = blockIdx.z;
    int idx = blockIdx.x * blockDim.x + threadIdx.x;
    if (idx >= TOK * DI) return;
    int tok = idx / DI;
    int d   = idx - tok * DI;
    int l   = tok & (SEQ - 1);
    const float* cw = (dir ? cw1 : cw0) + d * DCONV;
    float acc = (dir ? cb1 : cb0)[d];
    const float* xzp = xz + (size_t)dir * TOK * DI2 + (size_t)tok * DI2 + d;
    #pragma unroll
    for (int j = 0; j < DCONV; j++) {
        int lo = l - (DCONV - 1) + j;
        if (lo >= 0) acc = fmaf(cw[j], xzp[(long)(j - (DCONV - 1)) * DI2], acc);
    }
    float sg = 1.f / (1.f + __expf(-acc));
    xc[(size_t)dir * TOK * DI + idx] = acc * sg;
}

// ================= bcdt = xc @ xw, xw staged in smem =================
__global__ __launch_bounds__(256) void bcdt_kernel(
    const float* __restrict__ xc, const float* __restrict__ xw0,
    const float* __restrict__ xw1, float* __restrict__ bcdt)
{
    __shared__ float sw[256 * NX];   // 33 KB
    int dir  = blockIdx.z;
    int warp = threadIdx.x >> 5;
    int lane = threadIdx.x & 31;
    int tok  = blockIdx.x * 8 + warp;
    const float* xw = dir ? xw1 : xw0;
    const float* xr = xc + (size_t)dir * TOK * DI + (size_t)tok * DI;
    float acc = 0.f, acc32 = 0.f;
    for (int kc = 0; kc < DI; kc += 256) {
        __syncthreads();
        for (int i = threadIdx.x; i < 256 * NX; i += 256)
            sw[i] = xw[(size_t)kc * NX + i];
        __syncthreads();
        #pragma unroll 4
        for (int k = 0; k < 256; k += 4) {
            float4 xv = *reinterpret_cast<const float4*>(xr + kc + k);
            const float* wr = sw + k * NX;
            acc = fmaf(xv.x, wr[lane],          acc);
            acc = fmaf(xv.y, wr[NX + lane],     acc);
            acc = fmaf(xv.z, wr[2 * NX + lane], acc);
            acc = fmaf(xv.w, wr[3 * NX + lane], acc);
            if (lane == 0) {
                acc32 = fmaf(xv.x, wr[32],          acc32);
                acc32 = fmaf(xv.y, wr[NX + 32],     acc32);
                acc32 = fmaf(xv.z, wr[2 * NX + 32], acc32);
                acc32 = fmaf(xv.w, wr[3 * NX + 32], acc32);
            }
        }
    }
    float* orow = bcdt + ((size_t)dir * TOK + tok) * NX;
    orow[lane] = acc;
    if (lane == 0) orow[32] = acc32;
}

// ================= dt = softplus(...); u = dt*xc =================
__global__ __launch_bounds__(256) void dtu_kernel(
    const float* __restrict__ bcdt, const float* __restrict__ xc,
    const float* __restrict__ dtw0, const float* __restrict__ dtw1,
    const float* __restrict__ dtb0, const float* __restrict__ dtb1,
    float* __restrict__ dt, float* __restrict__ u)
{
    int dir = blockIdx.z;
    int idx = blockIdx.x * blockDim.x + threadIdx.x;
    if (idx >= TOK * DI) return;
    int tok = idx / DI;
    int d   = idx - tok * DI;
    float draw = bcdt[((size_t)dir * TOK + tok) * NX];
    float pre = fmaf(draw, (dir ? dtw1 : dtw0)[d], (dir ? dtb1 : dtb0)[d]);
    float dtv = (pre > 20.f) ? pre : log1pf(expf(pre));
    size_t o = (size_t)dir * TOK * DI + idx;
    dt[o] = dtv;
    u[o]  = dtv * xc[o];
}

// ================= selective scan =================
__global__ __launch_bounds__(256) void scan_kernel(
    const float* __restrict__ bcdt, const float* __restrict__ dt,
    const float* __restrict__ u, const float* __restrict__ Alog0,
    const float* __restrict__ Alog1, float* __restrict__ ys)
{
    int wg   = (blockIdx.x * blockDim.x + threadIdx.x) >> 5;  // 0..3071
    int lane = threadIdx.x & 31;
    int dir  = wg / 1536;
    int rem  = wg - dir * 1536;
    int b    = rem / 768;
    int wp   = rem - b * 768;
    int half = lane >> 4;
    int s    = lane & 15;
    int d    = wp * 2 + half;

    const float* Alog = dir ? Alog1 : Alog0;
    float al = Alog[d * NSTATE + s];
    al = fminf(fmaxf(al, -6.f), 6.f);
    float Aval = -__expf(al);

    size_t tokBase = (size_t)dir * TOK + (size_t)b * SEQ;
    const float* dtp  = dt   + tokBase * DI + d;
    const float* up   = u    + tokBase * DI + d;
    const float* rowp = bcdt + tokBase * NX;
    float* ysp        = ys   + tokBase * DI + d;

    float h = 0.f;
    float dtv = *dtp, uv = *up;
    float Bv = rowp[1 + s], Cv = rowp[17 + s];

    for (int t = 0; t < SEQ; ++t) {
        float a = __expf(dtv * Aval);
        float hb = fmaf(a, h, uv * Bv);
        hb = fminf(fmaxf(hb, -10000.f), 10000.f);
        h = hb;
        float p = h * Cv;
        if (t < SEQ - 1) {
            dtp += DI; up += DI; rowp += NX;
            dtv = *dtp; uv = *up;
            Bv = rowp[1 + s]; Cv = rowp[17 + s];
        }
        p += __shfl_xor_sync(0xffffffffu, p, 8);
        p += __shfl_xor_sync(0xffffffffu, p, 4);
        p += __shfl_xor_sync(0xffffffffu, p, 2);
        p += __shfl_xor_sync(0xffffffffu, p, 1);
        if (s == 0) *ysp = p;
        ysp += DI;
    }
}

// ================= gate: g = (ys + xc*Dp) * silu(z) -> bf16 hi/lo ==========
__global__ __launch_bounds__(256) void gate_kernel(
    const float* __restrict__ ys, const float* __restrict__ xc,
    const float* __restrict__ xz, const float* __restrict__ Dp0,
    const float* __restrict__ Dp1, bf16* __restrict__ gh, bf16* __restrict__ gl)
{
    int dir = blockIdx.z;
    int idx = blockIdx.x * blockDim.x + threadIdx.x;
    if (idx >= TOK * DI) return;
    int tok = idx / DI;
    int d   = idx - tok * DI;
    size_t o = (size_t)dir * TOK * DI + idx;
    float z = xz[(size_t)dir * TOK * DI2 + (size_t)tok * DI2 + DI + d];
    float sz = z / (1.f + __expf(-z));
    float y = fmaf(xc[o], (dir ? Dp1 : Dp0)[d], ys[o]);
    float v = y * sz;
    bf16 h = __float2bfloat16(v);
    gh[o] = h;
    gl[o] = __float2bfloat16(v - __bfloat162float(h));
}

// ================= combine =================
__global__ __launch_bounds__(256) void combine_kernel(
    const float* __restrict__ x, const float* __restrict__ alpha,
    const float* __restrict__ yp, float* __restrict__ out)
{
    int idx = blockIdx.x * blockDim.x + threadIdx.x;
    if (idx >= TOK * DM) return;
    int tok = idx / DM;
    int m   = idx - tok * DM;
    float a = 1.f / (1.f + __expf(-alpha[0]));
    int tokb = tok ^ (SEQ - 1);
    float yf = yp[idx];
    float yb = yp[(size_t)TOK * DM + (size_t)tokb * DM + m];
    out[idx] = fmaf(a, yf, fmaf(1.f - a, yb, x[idx]));
}

// ================= launch =================
extern "C" void kernel_launch(void* const* d_in, const int* in_sizes, int n_in,
                              void* d_out, int out_size)
{
    const float* x     = (const float*)d_in[0];
    const float* ln_g  = (const float*)d_in[1];
    const float* ln_b  = (const float*)d_in[2];
    const float* alpha = (const float*)d_in[3];
    const float* f_inw  = (const float*)d_in[4];
    const float* f_cw   = (const float*)d_in[5];
    const float* f_cb   = (const float*)d_in[6];
    const float* f_xw   = (const float*)d_in[7];
    const float* f_dtw  = (const float*)d_in[8];
    const float* f_dtb  = (const float*)d_in[9];
    const float* f_Alog = (const float*)d_in[10];
    const float* f_D    = (const float*)d_in[11];
    const float* f_outw = (const float*)d_in[12];
    const float* b_inw  = (const float*)d_in[13];
    const float* b_cw   = (const float*)d_in[14];
    const float* b_cb   = (const float*)d_in[15];
    const float* b_xw   = (const float*)d_in[16];
    const float* b_dtw  = (const float*)d_in[17];
    const float* b_dtb  = (const float*)d_in[18];
    const float* b_Alog = (const float*)d_in[19];
    const float* b_D    = (const float*)d_in[20];
    const float* b_outw = (const float*)d_in[21];
    float* out = (float*)d_out;

    bf16 *xnh, *xnl, *winh, *winl, *wouth, *woutl, *gh, *gl;
    float *xz, *xc, *bcdt, *dt, *u, *ys, *yp;
    cudaGetSymbolAddress((void**)&xnh,   g_xn_h);
    cudaGetSymbolAddress((void**)&xnl,   g_xn_l);
    cudaGetSymbolAddress((void**)&winh,  g_win_h);
    cudaGetSymbolAddress((void**)&winl,  g_win_l);
    cudaGetSymbolAddress((void**)&wouth, g_wout_h);
    cudaGetSymbolAddress((void**)&woutl, g_wout_l);
    cudaGetSymbolAddress((void**)&gh,    g_gh);
    cudaGetSymbolAddress((void**)&gl,    g_gl);
    cudaGetSymbolAddress((void**)&xz,    g_xz);
    cudaGetSymbolAddress((void**)&xc,    g_xc);
    cudaGetSymbolAddress((void**)&bcdt,  g_bcdt);
    cudaGetSymbolAddress((void**)&dt,    g_dt);
    cudaGetSymbolAddress((void**)&u,     g_u);
    cudaGetSymbolAddress((void**)&ys,    g_ys);
    cudaGetSymbolAddress((void**)&yp,    g_yp);

    const int smemGemm = NSTG * STAGE_B;   // 192 KB, 3-stage
    cudaFuncSetAttribute(mma_gemm, cudaFuncAttributeMaxDynamicSharedMemorySize, smemGemm);

    // 1) layernorm -> bf16 hi/lo
    ln_kernel<<<TOK, 256>>>(x, ln_g, ln_b, xnh, xnl);

    // 2) weight transpose + split (both dirs)
    wsplit_kernel<<<dim3(DI2 / 32, DM / 32, 2), dim3(32, 8)>>>(
        f_inw, b_inw, winh, winl, DM, DI2);
    wsplit_kernel<<<dim3(DM / 32, DI / 32, 2), dim3(32, 8)>>>(
        f_outw, b_outw, wouth, woutl, DI, DM);

    // 3) in-proj GEMM; dir 1 reads time-flipped rows
    mma_gemm<<<dim3(DI2 / 128, TOK / 128, 2), 512, smemGemm>>>(
        xnh, xnl, winh, winl, xz, TOK, DI2, DM, /*aPerDir=*/0, /*flipA=*/1);

    // 4) depthwise conv + SiLU
    conv_silu_kernel<<<dim3((TOK * DI) / 256, 1, 2), 256>>>(
        xz, f_cw, b_cw, f_cb, b_cb, xc);

    // 5) bcdt
    bcdt_kernel<<<dim3(TOK / 8, 1, 2), 256>>>(xc, f_xw, b_xw, bcdt);

    // 6) dt/u precompute
    dtu_kernel<<<dim3((TOK * DI) / 256, 1, 2), 256>>>(
        bcdt, xc, f_dtw, b_dtw, f_dtb, b_dtb, dt, u);

    // 7) selective scan
    scan_kernel<<<384, 256>>>(bcdt, dt, u, f_Alog, b_Alog, ys);

    // 8) gate -> bf16 hi/lo
    gate_kernel<<<dim3((TOK * DI) / 256, 1, 2), 256>>>(
        ys, xc, xz, f_D, b_D, gh, gl);

    // 9) out-proj GEMM
    mma_gemm<<<dim3(DM / 128, TOK / 128, 2), 512, smemGemm>>>(
        gh, gl, wouth, woutl, yp, TOK, DM, DI, /*aPerDir=*/1, /*flipA=*/0);

    // 10) combine + residual
    combine_kernel<<<(TOK * DM) / 256, 256>>>(x, alpha, yp, out);
}

// round 7
// speedup vs baseline: 1.1652x; 1.0489x over previous
#include <cuda_runtime.h>
#include <cuda_bf16.h>
#include <cstdint>

// ---------------- problem constants ----------------
#define BATCH   2
#define SEQ     2048
#define TOK     (BATCH * SEQ)        // 4096
#define DM      768                  // d_model
#define DI      1536                 // d_inner
#define DI2     (2 * DI)             // 3072
#define NSTATE  16
#define NX      33                   // 1 + 2*NSTATE
#define DCONV   4

typedef __nv_bfloat16 bf16;

// ---------------- scratch (static device globals) --------
__device__ __align__(16) bf16  g_xn_h [TOK * DM];
__device__ __align__(16) bf16  g_xn_l [TOK * DM];
__device__ __align__(16) bf16  g_win_h[2ll * DI2 * DM];   // [dir][N=3072][K=768]
__device__ __align__(16) bf16  g_win_l[2ll * DI2 * DM];
__device__ __align__(16) bf16  g_wout_h[2ll * DM * DI];   // [dir][N=768][K=1536]
__device__ __align__(16) bf16  g_wout_l[2ll * DM * DI];
__device__ __align__(16) bf16  g_gh [2ll * TOK * DI];
__device__ __align__(16) bf16  g_gl [2ll * TOK * DI];
__device__ float g_xz  [2ll * TOK * DI2];
__device__ float g_xc  [2ll * TOK * DI];
__device__ float g_bcdt[2ll * TOK * NX];
__device__ float g_dt  [2ll * TOK * DI];
__device__ float g_u   [2ll * TOK * DI];
__device__ float g_ys  [2ll * TOK * DI];
__device__ float g_yp  [2ll * TOK * DM];

// ================= helpers =================
__device__ __forceinline__ uint32_t s2u(const void* p) {
    uint32_t a;
    asm("{ .reg .u64 t; cvta.to.shared.u64 t, %1; cvt.u32.u64 %0, t; }"
        : "=r"(a) : "l"(p));
    return a;
}
__device__ __forceinline__ uint32_t swz(uint32_t off) {
    return off ^ ((off >> 3) & 0x70);
}
__device__ __forceinline__ void cpasync16(uint32_t dst, const void* src) {
    asm volatile("cp.async.cg.shared.global [%0], [%1], 16;" :: "r"(dst), "l"(src) : "memory");
}
#define CP_COMMIT() asm volatile("cp.async.commit_group;" ::: "memory")
#define CP_WAIT0()  asm volatile("cp.async.wait_group 0;" ::: "memory")
#define CP_WAIT1()  asm volatile("cp.async.wait_group 1;" ::: "memory")

__device__ __forceinline__ void ldsm4(uint32_t* r, uint32_t addr) {
    asm volatile("ldmatrix.sync.aligned.m8n8.x4.shared.b16 {%0,%1,%2,%3}, [%4];"
                 : "=r"(r[0]), "=r"(r[1]), "=r"(r[2]), "=r"(r[3]) : "r"(addr));
}
__device__ __forceinline__ void mma16816(float* c, const uint32_t* a,
                                         uint32_t b0, uint32_t b1) {
    asm volatile(
        "mma.sync.aligned.m16n8k16.row.col.f32.bf16.bf16.f32 "
        "{%0,%1,%2,%3}, {%4,%5,%6,%7}, {%8,%9}, {%0,%1,%2,%3};"
        : "+f"(c[0]), "+f"(c[1]), "+f"(c[2]), "+f"(c[3])
        : "r"(a[0]), "r"(a[1]), "r"(a[2]), "r"(a[3]), "r"(b0), "r"(b1));
}

// ================= mma.sync GEMM (bf16 split precision, 512 threads) =======
// C[dir][M][N] (fp32) = A(hi+lo)[M][K] @ B(hi+lo)[dir][N][K]^T
// passes==3: AhBh + AhBl + AlBh.  passes==2: AhBh + AlBh (= A·Bh exactly).
// 128x128 tile, K chunk 64, 3-stage cp.async, 16 warps (4M x 4N).
// Warp-staggered ks phase + single barrier per chunk to break LDSM/MMA lockstep.
#define BK 64
#define TILE_B 16384                 // 128 rows x 128 bytes
#define STAGE_B (4 * TILE_B)         // Ah, Al, Bh, Bl
#define NSTG 3

__global__ __launch_bounds__(512, 1)
void mma_gemm(const bf16* __restrict__ Ah, const bf16* __restrict__ Al,
              const bf16* __restrict__ Bh, const bf16* __restrict__ Bl,
              float* __restrict__ C, int M, int N, int K, int aPerDir, int flipA,
              int passes)
{
    extern __shared__ __align__(1024) char smem[];
    const int dir   = blockIdx.z;
    const int mBase = blockIdx.y * 128;
    const int nBase = blockIdx.x * 128;
    const uint32_t sb = s2u(smem);
    const int tid = threadIdx.x, wid = tid >> 5, lane = tid & 31;
    const int wm = wid & 3, wn = wid >> 2;

    const bf16* Ahp = Ah + (aPerDir ? (size_t)dir * M * K : 0);
    const bf16* Alp = Al + (aPerDir ? (size_t)dir * M * K : 0);
    const bf16* Bhp = Bh + (size_t)dir * (size_t)N * K;
    const bf16* Blp = Bl + (size_t)dir * (size_t)N * K;

    const int CK = K / BK;

    float acc[2][4][4];
    #pragma unroll
    for (int i = 0; i < 2; i++)
        #pragma unroll
        for (int j = 0; j < 4; j++)
            #pragma unroll
            for (int q = 0; q < 4; q++) acc[i][j][q] = 0.f;

    auto issue = [&](int c, int st) {
        const int k0 = c * BK;
        #pragma unroll
        for (int i = 0; i < 8; ++i) {
            int q     = tid + 512 * i;
            int which = q >> 10;            // 0 Ah, 1 Al, 2 Bh, 3 Bl
            int t     = q & 1023;
            int row   = t >> 3;
            int kb    = t & 7;
            const bf16* src;
            if (which < 2) {
                int grow = mBase + row;
                if (flipA && dir) grow ^= (SEQ - 1);
                src = (which ? Alp : Ahp) + (size_t)grow * K + k0 + kb * 8;
            } else {
                src = ((which == 3) ? Blp : Bhp) + (size_t)(nBase + row) * K + k0 + kb * 8;
            }
            uint32_t dst = sb + st * STAGE_B + which * TILE_B +
                           swz((uint32_t)(row * 128 + kb * 16));
            cpasync16(dst, src);
        }
        CP_COMMIT();
    };

    issue(0, 0);
    issue(1, 1);

    const int g  = lane >> 3;    // 8x8-tile group 0..3
    const int lr = lane & 7;

    int stg = 0, stgNext = 2;
    for (int c = 0; c < CK; ++c) {
        if (c + 1 < CK) { CP_WAIT1(); } else { CP_WAIT0(); }
        __syncthreads();          // single barrier per chunk (3-stage ring safe)
        if (c + 2 < CK) {
            issue(c + 2, stgNext);
            if (++stgNext == NSTG) stgNext = 0;
        }

        const uint32_t tb = sb + stg * STAGE_B;
        if (++stg == NSTG) stg = 0;

        #pragma unroll
        for (int kss = 0; kss < 4; ++kss) {
            const int ks = (kss + wm) & 3;           // warp-staggered phase
            const int kByte = ks * 32 + (g >> 1) * 16;
            uint32_t ah[2][4], al[2][4], bh[2][4], bl[2][4];
            #pragma unroll
            for (int jj = 0; jj < 2; ++jj) {
                int row = wn * 32 + jj * 16 + (g & 1) * 8 + lr;
                uint32_t off = swz((uint32_t)(row * 128 + kByte));
                ldsm4(bh[jj], tb + 2 * TILE_B + off);
                if (passes == 3) ldsm4(bl[jj], tb + 3 * TILE_B + off);
            }
            #pragma unroll
            for (int i = 0; i < 2; ++i) {
                int row = wm * 32 + i * 16 + (g & 1) * 8 + lr;
                uint32_t off = swz((uint32_t)(row * 128 + kByte));
                ldsm4(ah[i], tb + off);
                ldsm4(al[i], tb + TILE_B + off);
            }
            #pragma unroll
            for (int i = 0; i < 2; ++i)
                #pragma unroll
                for (int jj = 0; jj < 2; ++jj) {
                    mma16816(acc[i][2*jj],   ah[i], bh[jj][0], bh[jj][2]);
                    mma16816(acc[i][2*jj+1], ah[i], bh[jj][1], bh[jj][3]);
                }
            if (passes == 3) {
                #pragma unroll
                for (int i = 0; i < 2; ++i)
                    #pragma unroll
                    for (int jj = 0; jj < 2; ++jj) {
                        mma16816(acc[i][2*jj],   ah[i], bl[jj][0], bl[jj][2]);
                        mma16816(acc[i][2*jj+1], ah[i], bl[jj][1], bl[jj][3]);
                    }
            }
            #pragma unroll
            for (int i = 0; i < 2; ++i)
                #pragma unroll
                for (int jj = 0; jj < 2; ++jj) {
                    mma16816(acc[i][2*jj],   al[i], bh[jj][0], bh[jj][2]);
                    mma16816(acc[i][2*jj+1], al[i], bh[jj][1], bh[jj][3]);
                }
        }
    }

    // epilogue: direct STG
    float* Cp = C + (size_t)dir * (size_t)M * N;
    #pragma unroll
    for (int i = 0; i < 2; ++i) {
        int r0 = mBase + wm * 32 + i * 16 + (lane >> 2);
        #pragma unroll
        for (int j = 0; j < 4; ++j) {
            int col = nBase + wn * 32 + j * 8 + (lane & 3) * 2;
            float2 v0 = make_float2(acc[i][j][0], acc[i][j][1]);
            float2 v1 = make_float2(acc[i][j][2], acc[i][j][3]);
            *reinterpret_cast<float2*>(Cp + (size_t)r0 * N + col)       = v0;
            *reinterpret_cast<float2*>(Cp + (size_t)(r0 + 8) * N + col) = v1;
        }
    }
}

// ================= layernorm -> bf16 hi/lo =================
__device__ __forceinline__ float block_sum(float v, float* sh) {
    int lane = threadIdx.x & 31, w = threadIdx.x >> 5;
    #pragma unroll
    for (int o = 16; o; o >>= 1) v += __shfl_xor_sync(0xffffffffu, v, o);
    if (lane == 0) sh[w] = v;
    __syncthreads();
    if (w == 0) {
        float x = (lane < 8) ? sh[lane] : 0.f;
        #pragma unroll
        for (int o = 4; o; o >>= 1) x += __shfl_xor_sync(0xffffffffu, x, o);
        if (lane == 0) sh[0] = x;
    }
    __syncthreads();
    float r = sh[0];
    __syncthreads();
    return r;
}

__global__ __launch_bounds__(256) void ln_kernel(
    const float* __restrict__ x, const float* __restrict__ gam,
    const float* __restrict__ bet, bf16* __restrict__ xh, bf16* __restrict__ xl)
{
    __shared__ float sh[8];
    int tok = blockIdx.x;
    const float* xr = x + (size_t)tok * DM;
    int tid = threadIdx.x;
    float v0 = xr[tid], v1 = xr[tid + 256], v2 = xr[tid + 512];
    float s = block_sum(v0 + v1 + v2, sh);
    float mu = s * (1.0f / DM);
    float d0 = v0 - mu, d1 = v1 - mu, d2 = v2 - mu;
    float vs = block_sum(d0 * d0 + d1 * d1 + d2 * d2, sh);
    float inv = rsqrtf(vs * (1.0f / DM) + 1e-5f);
    size_t ob = (size_t)tok * DM;
    #pragma unroll
    for (int p = 0; p < 3; ++p) {
        int i = tid + p * 256;
        float d = (p == 0 ? d0 : p == 1 ? d1 : d2);
        float val = d * inv * gam[i] + bet[i];
        bf16 h = __float2bfloat16(val);
        xh[ob + i] = h;
        xl[ob + i] = __float2bfloat16(val - __bfloat162float(h));
    }
}

// ================= weight transpose + bf16 split =================
__global__ void wsplit_kernel(const float* __restrict__ w0, const float* __restrict__ w1,
                              bf16* __restrict__ th, bf16* __restrict__ tl, int K, int N)
{
    __shared__ float t[32][33];
    int dir = blockIdx.z;
    const float* w = dir ? w1 : w0;
    int k0 = blockIdx.y * 32, n0 = blockIdx.x * 32;
    int tx = threadIdx.x, ty = threadIdx.y;
    #pragma unroll
    for (int i = 0; i < 4; ++i)
        t[ty + 8 * i][tx] = w[(size_t)(k0 + ty + 8 * i) * N + n0 + tx];
    __syncthreads();
    bf16* thp = th + (size_t)dir * N * K;
    bf16* tlp = tl + (size_t)dir * N * K;
    #pragma unroll
    for (int i = 0; i < 4; ++i) {
        int n = n0 + ty + 8 * i, k = k0 + tx;
        float v = t[tx][ty + 8 * i];
        bf16 h = __float2bfloat16(v);
        thp[(size_t)n * K + k] = h;
        tlp[(size_t)n * K + k] = __float2bfloat16(v - __bfloat162float(h));
    }
}

// ================= depthwise causal conv (k=4) + bias + SiLU =================
__global__ __launch_bounds__(256) void conv_silu_kernel(
    const float* __restrict__ xz, const float* __restrict__ cw0,
    const float* __restrict__ cw1, const float* __restrict__ cb0,
    const float* __restrict__ cb1, float* __restrict__ xc)
{
    int dir = blockIdx.z;
    int idx = blockIdx.x * blockDim.x + threadIdx.x;
    if (idx >= TOK * DI) return;
    int tok = idx / DI;
    int d   = idx - tok * DI;
    int l   = tok & (SEQ - 1);
    const float* cw = (dir ? cw1 : cw0) + d * DCONV;
    float acc = (dir ? cb1 : cb0)[d];
    const float* xzp = xz + (size_t)dir * TOK * DI2 + (size_t)tok * DI2 + d;
    #pragma unroll
    for (int j = 0; j < DCONV; j++) {
        int lo = l - (DCONV - 1) + j;
        if (lo >= 0) acc = fmaf(cw[j], xzp[(long)(j - (DCONV - 1)) * DI2], acc);
    }
    float sg = 1.f / (1.f + __expf(-acc));
    xc[(size_t)dir * TOK * DI + idx] = acc * sg;
}

// ================= bcdt = xc @ xw, xw staged in smem =================
__global__ __launch_bounds__(256) void bcdt_kernel(
    const float* __restrict__ xc, const float* __restrict__ xw0,
    const float* __restrict__ xw1, float* __restrict__ bcdt)
{
    __shared__ float sw[256 * NX];   // 33 KB
    int dir  = blockIdx.z;
    int warp = threadIdx.x >> 5;
    int lane = threadIdx.x & 31;
    int tok  = blockIdx.x * 8 + warp;
    const float* xw = dir ? xw1 : xw0;
    const float* xr = xc + (size_t)dir * TOK * DI + (size_t)tok * DI;
    float acc = 0.f, acc32 = 0.f;
    for (int kc = 0; kc < DI; kc += 256) {
        __syncthreads();
        for (int i = threadIdx.x; i < 256 * NX; i += 256)
            sw[i] = xw[(size_t)kc * NX + i];
        __syncthreads();
        #pragma unroll 4
        for (int k = 0; k < 256; k += 4) {
            float4 xv = *reinterpret_cast<const float4*>(xr + kc + k);
            const float* wr = sw + k * NX;
            acc = fmaf(xv.x, wr[lane],          acc);
            acc = fmaf(xv.y, wr[NX + lane],     acc);
            acc = fmaf(xv.z, wr[2 * NX + lane], acc);
            acc = fmaf(xv.w, wr[3 * NX + lane], acc);
            if (lane == 0) {
                acc32 = fmaf(xv.x, wr[32],          acc32);
                acc32 = fmaf(xv.y, wr[NX + 32],     acc32);
                acc32 = fmaf(xv.z, wr[2 * NX + 32], acc32);
                acc32 = fmaf(xv.w, wr[3 * NX + 32], acc32);
            }
        }
    }
    float* orow = bcdt + ((size_t)dir * TOK + tok) * NX;
    orow[lane] = acc;
    if (lane == 0) orow[32] = acc32;
}

// ================= dt = softplus(...); u = dt*xc =================
__global__ __launch_bounds__(256) void dtu_kernel(
    const float* __restrict__ bcdt, const float* __restrict__ xc,
    const float* __restrict__ dtw0, const float* __restrict__ dtw1,
    const float* __restrict__ dtb0, const float* __restrict__ dtb1,
    float* __restrict__ dt, float* __restrict__ u)
{
    int dir = blockIdx.z;
    int idx = blockIdx.x * blockDim.x + threadIdx.x;
    if (idx >= TOK * DI) return;
    int tok = idx / DI;
    int d   = idx - tok * DI;
    float draw = bcdt[((size_t)dir * TOK + tok) * NX];
    float pre = fmaf(draw, (dir ? dtw1 : dtw0)[d], (dir ? dtb1 : dtb0)[d]);
    float dtv = (pre > 20.f) ? pre : log1pf(expf(pre));
    size_t o = (size_t)dir * TOK * DI + idx;
    dt[o] = dtv;
    u[o]  = dtv * xc[o];
}

// ================= selective scan =================
__global__ __launch_bounds__(256) void scan_kernel(
    const float* __restrict__ bcdt, const float* __restrict__ dt,
    const float* __restrict__ u, const float* __restrict__ Alog0,
    const float* __restrict__ Alog1, float* __restrict__ ys)
{
    int wg   = (blockIdx.x * blockDim.x + threadIdx.x) >> 5;  // 0..3071
    int lane = threadIdx.x & 31;
    int dir  = wg / 1536;
    int rem  = wg - dir * 1536;
    int b    = rem / 768;
    int wp   = rem - b * 768;
    int half = lane >> 4;
    int s    = lane & 15;
    int d    = wp * 2 + half;

    const float* Alog = dir ? Alog1 : Alog0;
    float al = Alog[d * NSTATE + s];
    al = fminf(fmaxf(al, -6.f), 6.f);
    float Aval = -__expf(al);

    size_t tokBase = (size_t)dir * TOK + (size_t)b * SEQ;
    const float* dtp  = dt   + tokBase * DI + d;
    const float* up   = u    + tokBase * DI + d;
    const float* rowp = bcdt + tokBase * NX;
    float* ysp        = ys   + tokBase * DI + d;

    float h = 0.f;
    float dtv = *dtp, uv = *up;
    float Bv = rowp[1 + s], Cv = rowp[17 + s];

    for (int t = 0; t < SEQ; ++t) {
        float a = __expf(dtv * Aval);
        float hb = fmaf(a, h, uv * Bv);
        hb = fminf(fmaxf(hb, -10000.f), 10000.f);
        h = hb;
        float p = h * Cv;
        if (t < SEQ - 1) {
            dtp += DI; up += DI; rowp += NX;
            dtv = *dtp; uv = *up;
            Bv = rowp[1 + s]; Cv = rowp[17 + s];
        }
        p += __shfl_xor_sync(0xffffffffu, p, 8);
        p += __shfl_xor_sync(0xffffffffu, p, 4);
        p += __shfl_xor_sync(0xffffffffu, p, 2);
        p += __shfl_xor_sync(0xffffffffu, p, 1);
        if (s == 0) *ysp = p;
        ysp += DI;
    }
}

// ================= gate: g = (ys + xc*Dp) * silu(z) -> bf16 hi/lo ==========
__global__ __launch_bounds__(256) void gate_kernel(
    const float* __restrict__ ys, const float* __restrict__ xc,
    const float* __restrict__ xz, const float* __restrict__ Dp0,
    const float* __restrict__ Dp1, bf16* __restrict__ gh, bf16* __restrict__ gl)
{
    int dir = blockIdx.z;
    int idx = blockIdx.x * blockDim.x + threadIdx.x;
    if (idx >= TOK * DI) return;
    int tok = idx / DI;
    int d   = idx - tok * DI;
    size_t o = (size_t)dir * TOK * DI + idx;
    float z = xz[(size_t)dir * TOK * DI2 + (size_t)tok * DI2 + DI + d];
    float sz = z / (1.f + __expf(-z));
    float y = fmaf(xc[o], (dir ? Dp1 : Dp0)[d], ys[o]);
    float v = y * sz;
    bf16 h = __float2bfloat16(v);
    gh[o] = h;
    gl[o] = __float2bfloat16(v - __bfloat162float(h));
}

// ================= combine =================
__global__ __launch_bounds__(256) void combine_kernel(
    const float* __restrict__ x, const float* __restrict__ alpha,
    const float* __restrict__ yp, float* __restrict__ out)
{
    int idx = blockIdx.x * blockDim.x + threadIdx.x;
    if (idx >= TOK * DM) return;
    int tok = idx / DM;
    int m   = idx - tok * DM;
    float a = 1.f / (1.f + __expf(-alpha[0]));
    int tokb = tok ^ (SEQ - 1);
    float yf = yp[idx];
    float yb = yp[(size_t)TOK * DM + (size_t)tokb * DM + m];
    out[idx] = fmaf(a, yf, fmaf(1.f - a, yb, x[idx]));
}

// ================= launch =================
extern "C" void kernel_launch(void* const* d_in, const int* in_sizes, int n_in,
                              void* d_out, int out_size)
{
    const float* x     = (const float*)d_in[0];
    const float* ln_g  = (const float*)d_in[1];
    const float* ln_b  = (const float*)d_in[2];
    const float* alpha = (const float*)d_in[3];
    const float* f_inw  = (const float*)d_in[4];
    const float* f_cw   = (const float*)d_in[5];
    const float* f_cb   = (const float*)d_in[6];
    const float* f_xw   = (const float*)d_in[7];
    const float* f_dtw  = (const float*)d_in[8];
    const float* f_dtb  = (const float*)d_in[9];
    const float* f_Alog = (const float*)d_in[10];
    const float* f_D    = (const float*)d_in[11];
    const float* f_outw = (const float*)d_in[12];
    const float* b_inw  = (const float*)d_in[13];
    const float* b_cw   = (const float*)d_in[14];
    const float* b_cb   = (const float*)d_in[15];
    const float* b_xw   = (const float*)d_in[16];
    const float* b_dtw  = (const float*)d_in[17];
    const float* b_dtb  = (const float*)d_in[18];
    const float* b_Alog = (const float*)d_in[19];
    const float* b_D    = (const float*)d_in[20];
    const float* b_outw = (const float*)d_in[21];
    float* out = (float*)d_out;

    bf16 *xnh, *xnl, *winh, *winl, *wouth, *woutl, *gh, *gl;
    float *xz, *xc, *bcdt, *dt, *u, *ys, *yp;
    cudaGetSymbolAddress((void**)&xnh,   g_xn_h);
    cudaGetSymbolAddress((void**)&xnl,   g_xn_l);
    cudaGetSymbolAddress((void**)&winh,  g_win_h);
    cudaGetSymbolAddress((void**)&winl,  g_win_l);
    cudaGetSymbolAddress((void**)&wouth, g_wout_h);
    cudaGetSymbolAddress((void**)&woutl, g_wout_l);
    cudaGetSymbolAddress((void**)&gh,    g_gh);
    cudaGetSymbolAddress((void**)&gl,    g_gl);
    cudaGetSymbolAddress((void**)&xz,    g_xz);
    cudaGetSymbolAddress((void**)&xc,    g_xc);
    cudaGetSymbolAddress((void**)&bcdt,  g_bcdt);
    cudaGetSymbolAddress((void**)&dt,    g_dt);
    cudaGetSymbolAddress((void**)&u,     g_u);
    cudaGetSymbolAddress((void**)&ys,    g_ys);
    cudaGetSymbolAddress((void**)&yp,    g_yp);

    const int smemGemm = NSTG * STAGE_B;   // 192 KB, 3-stage
    cudaFuncSetAttribute(mma_gemm, cudaFuncAttributeMaxDynamicSharedMemorySize, smemGemm);

    // 1) layernorm -> bf16 hi/lo
    ln_kernel<<<TOK, 256>>>(x, ln_g, ln_b, xnh, xnl);

    // 2) weight transpose + split (both dirs)
    wsplit_kernel<<<dim3(DI2 / 32, DM / 32, 2), dim3(32, 8)>>>(
        f_inw, b_inw, winh, winl, DM, DI2);
    wsplit_kernel<<<dim3(DM / 32, DI / 32, 2), dim3(32, 8)>>>(
        f_outw, b_outw, wouth, woutl, DI, DM);

    // 3) in-proj GEMM (3-pass); dir 1 reads time-flipped rows
    mma_gemm<<<dim3(DI2 / 128, TOK / 128, 2), 512, smemGemm>>>(
        xnh, xnl, winh, winl, xz, TOK, DI2, DM, /*aPerDir=*/0, /*flipA=*/1, 3);

    // 4) depthwise conv + SiLU
    conv_silu_kernel<<<dim3((TOK * DI) / 256, 1, 2), 256>>>(
        xz, f_cw, b_cw, f_cb, b_cb, xc);

    // 5) bcdt
    bcdt_kernel<<<dim3(TOK / 8, 1, 2), 256>>>(xc, f_xw, b_xw, bcdt);

    // 6) dt/u precompute
    dtu_kernel<<<dim3((TOK * DI) / 256, 1, 2), 256>>>(
        bcdt, xc, f_dtw, b_dtw, f_dtb, b_dtb, dt, u);

    // 7) selective scan
    scan_kernel<<<384, 256>>>(bcdt, dt, u, f_Alog, b_Alog, ys);

    // 8) gate -> bf16 hi/lo
    gate_kernel<<<dim3((TOK * DI) / 256, 1, 2), 256>>>(
        ys, xc, xz, f_D, b_D, gh, gl);

    // 9) out-proj GEMM (2-pass: exact A times rounded weights)
    mma_gemm<<<dim3(DM / 128, TOK / 128, 2), 512, smemGemm>>>(
        gh, gl, wouth, woutl, yp, TOK, DM, DI, /*aPerDir=*/1, /*flipA=*/0, 2);

    // 10) combine + residual
    combine_kernel<<<(TOK * DM) / 256, 256>>>(x, alpha, yp, out);
}